// round 15
// baseline (speedup 1.0000x reference)
#include <cuda_runtime.h>
#include <cstdint>

#define TSEQ  2048
#define CDIM  1024
#define NB    2
#define NHEAD 16
#define DHDIM 64
#define BTROWS (NB * TSEQ)   // 4096

typedef unsigned long long ull;

// Scratch for Q, K, V projections (flat (B*T, C) row-major == (B,H,T,Dh) view)
__device__ float g_q[NB * TSEQ * CDIM];
__device__ float g_k[NB * TSEQ * CDIM];
__device__ float g_v[NB * TSEQ * CDIM];

// ---------------- packed fp32x2 helpers (SASS FFMA2 path) -------------------
__device__ __forceinline__ ull bcast2(float x) {
    ull r; asm("mov.b64 %0, {%1, %1};" : "=l"(r) : "f"(x)); return r;
}
__device__ __forceinline__ ull pack2(float lo, float hi) {
    ull r; asm("mov.b64 %0, {%1, %2};" : "=l"(r) : "f"(lo), "f"(hi)); return r;
}
__device__ __forceinline__ float2 unpack2(ull v) {
    float2 r; asm("mov.b64 {%0, %1}, %2;" : "=f"(r.x), "=f"(r.y) : "l"(v)); return r;
}
__device__ __forceinline__ void ffma2(ull& d, ull a, ull b) {
    asm("fma.rn.f32x2 %0, %1, %2, %0;" : "+l"(d) : "l"(a), "l"(b));
}
__device__ __forceinline__ void fmul2(ull& d, ull a) {
    asm("mul.rn.f32x2 %0, %0, %1;" : "+l"(d) : "l"(a));
}

// ---------------- tf32 mma.sync helpers (plain compute_103 PTX) -------------
__device__ __forceinline__ uint32_t f2tf32(float f) {
    uint32_t u; asm("cvt.rna.tf32.f32 %0, %1;" : "=r"(u) : "f"(f)); return u;
}
__device__ __forceinline__ void split_tf32(float x, uint32_t& hi, uint32_t& lo) {
    uint32_t h = f2tf32(x);
    lo = f2tf32(x - __uint_as_float(h));
    hi = h;
}
__device__ __forceinline__ void mma_tf32(float& c0, float& c1, float& c2, float& c3,
                                         uint32_t a0, uint32_t a1, uint32_t a2, uint32_t a3,
                                         uint32_t b0, uint32_t b1) {
    asm volatile(
        "mma.sync.aligned.m16n8k8.row.col.f32.tf32.tf32.f32 "
        "{%0,%1,%2,%3}, {%4,%5,%6,%7}, {%8,%9}, {%0,%1,%2,%3};"
        : "+f"(c0), "+f"(c1), "+f"(c2), "+f"(c3)
        : "r"(a0), "r"(a1), "r"(a2), "r"(a3), "r"(b0), "r"(b1));
}

// ---------------------------------------------------------------------------
// QKV projection, 3xTF32 mma.sync (unchanged, known-good R11).
// ---------------------------------------------------------------------------
#define GBK 16
#define GNK (CDIM / GBK)          // 64 stages
#define GSTRIDE 20
#define GTILE (128 * GSTRIDE)     // floats per tile-buffer
#define GSMEM_FLOATS (8 * GTILE)  // Ah,Al,Bh,Bl x 2 buffers
#define GSMEM_BYTES (GSMEM_FLOATS * 4)   // 81920

__global__ __launch_bounds__(256, 2)
void qkv_mma_kernel(const float* __restrict__ X,
                    const float* __restrict__ Wq,
                    const float* __restrict__ Wk,
                    const float* __restrict__ Wv) {
    extern __shared__ float sm[];
    float* __restrict__ sAh = sm;
    float* __restrict__ sAl = sm + 2 * GTILE;
    float* __restrict__ sBh = sm + 4 * GTILE;
    float* __restrict__ sBl = sm + 6 * GTILE;

    const float* __restrict__ W =
        (blockIdx.z == 0) ? Wq : (blockIdx.z == 1) ? Wk : Wv;
    float* __restrict__ dst =
        (blockIdx.z == 0) ? g_q : (blockIdx.z == 1) ? g_k : g_v;

    const int m0  = blockIdx.x * 128;
    const int n0  = blockIdx.y * 128;
    const int tid = threadIdx.x;
    const int wid = tid >> 5;
    const int lane = tid & 31;
    const int g = lane >> 2;
    const int t = lane & 3;
    const int wm = (wid >> 2) * 64;
    const int wn = (wid & 3) * 32;

    const int mrow = tid >> 2;
    const int kq   = (tid & 3) << 2;
    const float* Abase = X + (size_t)(m0 + mrow) * CDIM + kq;
    const float* Bbase = W + (size_t)(n0 + mrow) * CDIM + kq;

    float c[4][4][4];
    #pragma unroll
    for (int mi = 0; mi < 4; mi++)
        #pragma unroll
        for (int ni = 0; ni < 4; ni++)
            #pragma unroll
            for (int e = 0; e < 4; e++) c[mi][ni][e] = 0.0f;

    float4 pa[2], pb[2];
    #pragma unroll
    for (int i = 0; i < 2; i++) {
        pa[i] = *(const float4*)(Abase + (size_t)(64 * i) * CDIM);
        pb[i] = *(const float4*)(Bbase + (size_t)(64 * i) * CDIM);
    }
    #pragma unroll
    for (int i = 0; i < 2; i++) {
        int adr = (mrow + 64 * i) * GSTRIDE + kq;
        uint4 h, l;
        split_tf32(pa[i].x, h.x, l.x); split_tf32(pa[i].y, h.y, l.y);
        split_tf32(pa[i].z, h.z, l.z); split_tf32(pa[i].w, h.w, l.w);
        *(uint4*)&sAh[adr] = h; *(uint4*)&sAl[adr] = l;
        split_tf32(pb[i].x, h.x, l.x); split_tf32(pb[i].y, h.y, l.y);
        split_tf32(pb[i].z, h.z, l.z); split_tf32(pb[i].w, h.w, l.w);
        *(uint4*)&sBh[adr] = h; *(uint4*)&sBl[adr] = l;
    }
    __syncthreads();

    for (int s = 0; s < GNK; s++) {
        const int buf = s & 1;
        const bool more = (s + 1 < GNK);
        if (more) {
            const int k0 = (s + 1) * GBK;
            #pragma unroll
            for (int i = 0; i < 2; i++) {
                pa[i] = *(const float4*)(Abase + (size_t)(64 * i) * CDIM + k0);
                pb[i] = *(const float4*)(Bbase + (size_t)(64 * i) * CDIM + k0);
            }
        }

        const float* Ah = sAh + buf * GTILE;
        const float* Al = sAl + buf * GTILE;
        const float* Bh = sBh + buf * GTILE;
        const float* Bl = sBl + buf * GTILE;

        #pragma unroll
        for (int ks = 0; ks < 2; ks++) {
            const int k0 = ks * 8;
            uint32_t ah[4][4], bh[4][2];
            #pragma unroll
            for (int mi = 0; mi < 4; mi++) {
                int r0 = (wm + mi * 16 + g) * GSTRIDE + k0 + t;
                ah[mi][0] = __float_as_uint(Ah[r0]);
                ah[mi][1] = __float_as_uint(Ah[r0 + 8 * GSTRIDE]);
                ah[mi][2] = __float_as_uint(Ah[r0 + 4]);
                ah[mi][3] = __float_as_uint(Ah[r0 + 8 * GSTRIDE + 4]);
            }
            #pragma unroll
            for (int ni = 0; ni < 4; ni++) {
                int b0 = (wn + ni * 8 + g) * GSTRIDE + k0 + t;
                bh[ni][0] = __float_as_uint(Bh[b0]);
                bh[ni][1] = __float_as_uint(Bh[b0 + 4]);
            }
            #pragma unroll
            for (int mi = 0; mi < 4; mi++)
                #pragma unroll
                for (int ni = 0; ni < 4; ni++)
                    mma_tf32(c[mi][ni][0], c[mi][ni][1], c[mi][ni][2], c[mi][ni][3],
                             ah[mi][0], ah[mi][1], ah[mi][2], ah[mi][3],
                             bh[ni][0], bh[ni][1]);

            uint32_t bl[4][2];
            #pragma unroll
            for (int ni = 0; ni < 4; ni++) {
                int b0 = (wn + ni * 8 + g) * GSTRIDE + k0 + t;
                bl[ni][0] = __float_as_uint(Bl[b0]);
                bl[ni][1] = __float_as_uint(Bl[b0 + 4]);
            }
            #pragma unroll
            for (int mi = 0; mi < 4; mi++)
                #pragma unroll
                for (int ni = 0; ni < 4; ni++)
                    mma_tf32(c[mi][ni][0], c[mi][ni][1], c[mi][ni][2], c[mi][ni][3],
                             ah[mi][0], ah[mi][1], ah[mi][2], ah[mi][3],
                             bl[ni][0], bl[ni][1]);

            uint32_t al[4][4];
            #pragma unroll
            for (int mi = 0; mi < 4; mi++) {
                int r0 = (wm + mi * 16 + g) * GSTRIDE + k0 + t;
                al[mi][0] = __float_as_uint(Al[r0]);
                al[mi][1] = __float_as_uint(Al[r0 + 8 * GSTRIDE]);
                al[mi][2] = __float_as_uint(Al[r0 + 4]);
                al[mi][3] = __float_as_uint(Al[r0 + 8 * GSTRIDE + 4]);
            }
            #pragma unroll
            for (int mi = 0; mi < 4; mi++)
                #pragma unroll
                for (int ni = 0; ni < 4; ni++)
                    mma_tf32(c[mi][ni][0], c[mi][ni][1], c[mi][ni][2], c[mi][ni][3],
                             al[mi][0], al[mi][1], al[mi][2], al[mi][3],
                             bh[ni][0], bh[ni][1]);
        }

        if (more) {
            const int nb = buf ^ 1;
            float* dAh = sAh + nb * GTILE; float* dAl = sAl + nb * GTILE;
            float* dBh = sBh + nb * GTILE; float* dBl = sBl + nb * GTILE;
            #pragma unroll
            for (int i = 0; i < 2; i++) {
                int adr = (mrow + 64 * i) * GSTRIDE + kq;
                uint4 h, l;
                split_tf32(pa[i].x, h.x, l.x); split_tf32(pa[i].y, h.y, l.y);
                split_tf32(pa[i].z, h.z, l.z); split_tf32(pa[i].w, h.w, l.w);
                *(uint4*)&dAh[adr] = h; *(uint4*)&dAl[adr] = l;
                split_tf32(pb[i].x, h.x, l.x); split_tf32(pb[i].y, h.y, l.y);
                split_tf32(pb[i].z, h.z, l.z); split_tf32(pb[i].w, h.w, l.w);
                *(uint4*)&dBh[adr] = h; *(uint4*)&dBl[adr] = l;
            }
            __syncthreads();
        }
    }

    #pragma unroll
    for (int mi = 0; mi < 4; mi++) {
        int r0 = m0 + wm + mi * 16 + g;
        #pragma unroll
        for (int ni = 0; ni < 4; ni++) {
            int col = n0 + wn + ni * 8 + 2 * t;
            *(float2*)(dst + (size_t)r0 * CDIM + col) =
                make_float2(c[mi][ni][0], c[mi][ni][1]);
            *(float2*)(dst + (size_t)(r0 + 8) * CDIM + col) =
                make_float2(c[mi][ni][2], c[mi][ni][3]);
        }
    }
}

// ---------------------------------------------------------------------------
// Causal flash attention, fp32 packed f32x2. Key-tile 64 (was 128) so
// smem = 51 KB/CTA and __launch_bounds__(256,3) -> 3 CTAs/SM (24 warps).
// Block = 64 query rows x one (b,h). 256 threads (tx 0..15, ty 0..15).
// S cols per thread: tx+16jj (jj<4), packed pairs (tx+32p, tx+32p+16), p<2.
// Smem: Qs[64][68] | KsP: K[64][68] reused as P[64][64] | Vs[64][68].
// ---------------------------------------------------------------------------
#define SQ 68
#define ATTN_SMEM_FLOATS (3 * 64 * SQ)   // 13056 floats = 52224 B

__global__ __launch_bounds__(256, 3)
void attn_kernel(float* __restrict__ out) {
    extern __shared__ float sm[];
    float* __restrict__ Qs  = sm;               // [64][68]
    float* __restrict__ KsP = sm + 64 * SQ;     // K [64][68] / P [64][64]
    float* __restrict__ Vs  = KsP + 64 * SQ;    // [64][68]

    const int qi = (int)gridDim.x - 1 - (int)blockIdx.x;  // heavy tiles first
    const int bh = blockIdx.y;
    const int q0 = qi * 64;
    const size_t base = (size_t)bh * (TSEQ * DHDIM);
    const float* __restrict__ Qg = g_q + base + (size_t)q0 * DHDIM;
    const float* __restrict__ Kg = g_k + base;
    const float* __restrict__ Vg = g_v + base;
    float* __restrict__ Og = out + base + (size_t)q0 * DHDIM;

    const int tid = threadIdx.x;
    const int tx  = tid & 15;
    const int ty  = tid >> 4;

    // Load Q tile (64x64), natural layout, padded stride
    #pragma unroll
    for (int it = 0; it < 4; it++) {
        int lin = it * 1024 + tid * 4;
        int r = lin >> 6, c = lin & 63;
        *(float4*)&Qs[r * SQ + c] = *(const float4*)(Qg + lin);
    }

    ull oacc[4][2];
    float mrow[4], lrow[4];
    #pragma unroll
    for (int i = 0; i < 4; i++) {
        oacc[i][0] = 0ull; oacc[i][1] = 0ull;
        mrow[i] = -1e30f;  lrow[i] = 0.0f;
    }

    const float SCL = 0.125f * 1.4426950408889634f;  // 1/sqrt(64)*log2(e)
    const int nt = qi + 1;                            // 64-key tiles

    for (int j = 0; j < nt; j++) {
        __syncthreads();   // prior PV readers of KsP/Vs done (covers Qs on j=0)
        {
            const float* Kt = Kg + (size_t)j * 64 * DHDIM;
            const float* Vt = Vg + (size_t)j * 64 * DHDIM;
            #pragma unroll
            for (int it = 0; it < 4; it++) {
                int lin = it * 1024 + tid * 4;
                int r = lin >> 6, c = lin & 63;
                *(float4*)&KsP[r * SQ + c] = *(const float4*)(Kt + lin);
                *(float4*)&Vs[r * SQ + c]  = *(const float4*)(Vt + lin);
            }
        }
        __syncthreads();

        // ---- S = Q @ K^T, packed pairs over column-halves ----
        ull s2[4][2];
        #pragma unroll
        for (int i = 0; i < 4; i++) { s2[i][0] = 0ull; s2[i][1] = 0ull; }

        #pragma unroll 4
        for (int d4 = 0; d4 < DHDIM; d4 += 4) {
            float4 q4[4], ka[2], kb[2];
            #pragma unroll
            for (int i = 0; i < 4; i++)
                q4[i] = *(const float4*)&Qs[(ty + 16 * i) * SQ + d4];
            #pragma unroll
            for (int p = 0; p < 2; p++) {
                ka[p] = *(const float4*)&KsP[(tx + 32 * p) * SQ + d4];
                kb[p] = *(const float4*)&KsP[(tx + 32 * p + 16) * SQ + d4];
            }
            #pragma unroll
            for (int e = 0; e < 4; e++) {
                ull bp0 = pack2(((const float*)&ka[0])[e], ((const float*)&kb[0])[e]);
                ull bp1 = pack2(((const float*)&ka[1])[e], ((const float*)&kb[1])[e]);
                #pragma unroll
                for (int i = 0; i < 4; i++) {
                    ull a2 = bcast2(((const float*)&q4[i])[e]);
                    ffma2(s2[i][0], a2, bp0);
                    ffma2(s2[i][1], a2, bp1);
                }
            }
        }

        // ---- unpack, scale, causal mask ----
        // pair p -> cols (tx+32p, tx+32p+16) = jj {2p, 2p+1} with col = tx+16jj
        float s[4][4];
        #pragma unroll
        for (int i = 0; i < 4; i++) {
            float2 u0 = unpack2(s2[i][0]);
            float2 u1 = unpack2(s2[i][1]);
            s[i][0] = u0.x; s[i][1] = u0.y;
            s[i][2] = u1.x; s[i][3] = u1.y;
        }

        const bool diag = (j == qi);
        #pragma unroll
        for (int i = 0; i < 4; i++) {
            int rg = ty + 16 * i;           // local row (diag tile: col local too)
            #pragma unroll
            for (int jj = 0; jj < 4; jj++) {
                float v = s[i][jj] * SCL;
                if (diag) {
                    int cl = tx + ((jj & 1) << 4) + ((jj >> 1) << 5);
                    if (cl > rg) v = -1e30f;
                }
                s[i][jj] = v;
            }
        }

        // ---- online softmax (rows shared by 16 consecutive lanes) ----
        #pragma unroll
        for (int i = 0; i < 4; i++) {
            float mloc = fmaxf(fmaxf(s[i][0], s[i][1]), fmaxf(s[i][2], s[i][3]));
            #pragma unroll
            for (int off = 8; off >= 1; off >>= 1)
                mloc = fmaxf(mloc, __shfl_xor_sync(0xffffffffu, mloc, off));
            float mnew  = fmaxf(mrow[i], mloc);
            float alpha = exp2f(mrow[i] - mnew);
            mrow[i] = mnew;
            float rs = 0.0f;
            #pragma unroll
            for (int jj = 0; jj < 4; jj++) {
                float p = exp2f(s[i][jj] - mnew);
                s[i][jj] = p;
                rs += p;
            }
            #pragma unroll
            for (int off = 8; off >= 1; off >>= 1)
                rs += __shfl_xor_sync(0xffffffffu, rs, off);
            lrow[i] = lrow[i] * alpha + rs;
            ull al2 = bcast2(alpha);
            fmul2(oacc[i][0], al2);
            fmul2(oacc[i][1], al2);
        }

        __syncthreads();   // all K reads done before P overwrites KsP
        #pragma unroll
        for (int i = 0; i < 4; i++) {
            int rb = (ty + 16 * i) * 64;
            KsP[rb + tx]      = s[i][0];
            KsP[rb + tx + 16] = s[i][1];
            KsP[rb + tx + 32] = s[i][2];
            KsP[rb + tx + 48] = s[i][3];
        }
        __syncthreads();

        // ---- O += P @ V  (v pairs contiguous in dh; p broadcast-packed) ----
        #pragma unroll 4
        for (int c = 0; c < 64; c++) {
            ull v0 = *(const ull*)&Vs[c * SQ + 2 * tx];
            ull v1 = *(const ull*)&Vs[c * SQ + 2 * tx + 32];
            #pragma unroll
            for (int i = 0; i < 4; i++) {
                ull p2 = bcast2(KsP[(ty + 16 * i) * 64 + c]);
                ffma2(oacc[i][0], p2, v0);
                ffma2(oacc[i][1], p2, v1);
            }
        }
    }

    #pragma unroll
    for (int i = 0; i < 4; i++) {
        float inv = 1.0f / lrow[i];
        float2 u0 = unpack2(oacc[i][0]);
        float2 u1 = unpack2(oacc[i][1]);
        int r = ty + 16 * i;
        *(float2*)&Og[r * DHDIM + 2 * tx]      = make_float2(u0.x * inv, u0.y * inv);
        *(float2*)&Og[r * DHDIM + 2 * tx + 32] = make_float2(u1.x * inv, u1.y * inv);
    }
}

// ---------------------------------------------------------------------------
extern "C" void kernel_launch(void* const* d_in, const int* in_sizes, int n_in,
                              void* d_out, int out_size) {
    const float* x  = (const float*)d_in[0];
    const float* Wq = (const float*)d_in[1];
    const float* Wk = (const float*)d_in[2];
    const float* Wv = (const float*)d_in[3];
    float* out = (float*)d_out;

    static bool attr_done = false;
    if (!attr_done) {
        cudaFuncSetAttribute(attn_kernel,
                             cudaFuncAttributeMaxDynamicSharedMemorySize,
                             ATTN_SMEM_FLOATS * (int)sizeof(float));
        cudaFuncSetAttribute(qkv_mma_kernel,
                             cudaFuncAttributeMaxDynamicSharedMemorySize,
                             GSMEM_BYTES);
        attr_done = true;
    }

    dim3 ggrid(BTROWS / 128, CDIM / 128, 3);   // 32 x 8 x 3
    qkv_mma_kernel<<<ggrid, 256, GSMEM_BYTES>>>(x, Wq, Wk, Wv);

    dim3 agrid(TSEQ / 64, NB * NHEAD);         // 32 x 32
    attn_kernel<<<agrid, 256, ATTN_SMEM_FLOATS * (int)sizeof(float)>>>(out);

    (void)in_sizes; (void)n_in; (void)out_size;
}